// round 15
// baseline (speedup 1.0000x reference)
#include <cuda_runtime.h>
#include <cuda_fp16.h>
#include <math.h>
#include <stdint.h>

// ===========================================================================
// Actor_10505490006716 — HMMA (mma.sync fp16) with 2-plane fp32 split.
// Round 15: elementwise + big GEMM exactly R12 (best known). Whh/layer/head
// GEMMs switch to BM=128 x BN=256, NSTAGE=2, 128 thr, 2 CTAs/SM -> grids
// 256/192/64 CTAs = ONE wave each (was ~2), LDSM:MMA 1:8 (was 1:6).
// ===========================================================================

#define BATCH 4096
#define HID   512
#define G4    2048
#define INDIM 3072
#define NPRU  1536

__device__ __half g_XA [(size_t)2 * 8192 * 3072];
__device__ __half g_W1 [(size_t)2 * 2048 * 3072];   // reordered [i|g|o|f]
__device__ __half g_Whh[(size_t)2 * 2048 * 512];    // reordered [i|g|o|f]
__device__ __half g_W2 [(size_t)2 * 1536 * 512];
__device__ __half g_W3 [(size_t)2 * 1536 * 512];
__device__ __half g_W4 [(size_t)2 * 1536 * 512];
__device__ __half g_Wo [(size_t)2 * 512 * 512];
__device__ __half g_Hs [(size_t)2 * 4096 * 512];
__device__ float g_G [(size_t)8192 * 2048];         // G0 (4096x1536) | G1 (4096x2048)
__device__ float g_c1[(size_t)4096 * 512];
__device__ float g_bias[2048 + 3 * 1536];           // b1r (igof) | b2p | b3p | b4p

// ---- PTX helpers ------------------------------------------------------------
__device__ __forceinline__ uint32_t smem_u32(const void* p) {
    uint32_t a;
    asm("{ .reg .u64 t; cvta.to.shared.u64 t, %1; cvt.u32.u64 %0, t; }"
        : "=r"(a) : "l"(p));
    return a;
}
__device__ __forceinline__ void cp16(uint32_t dst, const void* src) {
    asm volatile("cp.async.cg.shared.global [%0], [%1], 16;"
                 :: "r"(dst), "l"(src));
}
#define CP_COMMIT() asm volatile("cp.async.commit_group;" ::: "memory")
#define CP_WAIT1()  asm volatile("cp.async.wait_group 1;" ::: "memory")

__device__ __forceinline__ void ldsm_x4(uint32_t& r0, uint32_t& r1,
                                        uint32_t& r2, uint32_t& r3,
                                        uint32_t addr) {
    asm volatile("ldmatrix.sync.aligned.m8n8.x4.shared.b16 {%0,%1,%2,%3}, [%4];"
                 : "=r"(r0), "=r"(r1), "=r"(r2), "=r"(r3) : "r"(addr));
}
__device__ __forceinline__ void mma16816(float* d, const uint32_t* a,
                                         const uint32_t* b) {
    asm volatile("mma.sync.aligned.m16n8k16.row.col.f32.f16.f16.f32 "
                 "{%0,%1,%2,%3}, {%4,%5,%6,%7}, {%8,%9}, {%0,%1,%2,%3};"
                 : "+f"(d[0]), "+f"(d[1]), "+f"(d[2]), "+f"(d[3])
                 : "r"(a[0]), "r"(a[1]), "r"(a[2]), "r"(a[3]),
                   "r"(b[0]), "r"(b[1]));
}
__device__ __forceinline__ uint32_t swz(uint32_t off) {
    return off ^ ((off >> 3) & 0x70);
}

// ---- fp16 2-plane splitting ---------------------------------------------------
__device__ __forceinline__ void split2(float a, __half& o0, __half& o1) {
    __half b0 = __float2half_rn(a);
    o0 = b0;
    o1 = __float2half_rn(a - __half2float(b0));
}

union Pack8 { __half2 h[4]; uint4 v; };

__device__ __forceinline__ void split8_store(const float* v,
                                             __half* P, size_t S,
                                             size_t idx8) {
    Pack8 p0, p1;
#pragma unroll
    for (int k = 0; k < 4; k++) {
        __half a0, a1, b0, b1;
        split2(v[2 * k], a0, a1);
        split2(v[2 * k + 1], b0, b1);
        p0.h[k].x = a0; p0.h[k].y = b0;
        p1.h[k].x = a1; p1.h[k].y = b1;
    }
    ((uint4*)P)[idx8] = p0.v;
    ((uint4*)(P + S))[idx8] = p1.v;
}

// X = concat(state[:,t], goal[:,t]) for t in {0,1}. 8 elems/thread (R12).
__global__ void __launch_bounds__(256)
split_x_kernel(const float* __restrict__ state,
               const float* __restrict__ goal,
               __half* __restrict__ P, size_t S)
{
    size_t idx8 = (size_t)blockIdx.x * 256 + threadIdx.x;
    if (idx8 >= (size_t)8192 * INDIM / 8) return;
    size_t e = idx8 * 8;
    int row = (int)(e / INDIM);
    int col = (int)(e % INDIM);
    int b = row & 4095, t = row >> 12;
    const float* src = (col < 2048)
        ? state + (size_t)(b * 4 + t) * 2048 + col
        : goal  + (size_t)(b * 4 + t) * 1024 + (col - 2048);
    float v[8];
    *(float4*)v = *(const float4*)src;
    *(float4*)(v + 4) = *(const float4*)(src + 4);
    split8_store(v, P, S, idx8);
}

// generic weight split with row remap (R12, 8 elems/thread).
// mapMode 0: identity. mapMode 2: out [i|g|o|f] from src [i|f|g|o]
__global__ void __launch_bounds__(256)
split_w_map_kernel(const float* __restrict__ src,
                   __half* __restrict__ P, size_t S,
                   int rows, int K, int mapMode)
{
    size_t idx8 = (size_t)blockIdx.x * 256 + threadIdx.x;
    if (idx8 >= (size_t)rows * K / 8) return;
    size_t e = idx8 * 8;
    int row = (int)(e / K);
    int col = (int)(e % K);
    int srow = row;
    if (mapMode == 2)
        srow = (row < 512) ? row : ((row < 1536) ? row + 512 : row - 1024);
    const float* s = src + (size_t)srow * K + col;
    float v[8];
    *(float4*)v = *(const float4*)s;
    *(float4*)(v + 4) = *(const float4*)(s + 4);
    split8_store(v, P, S, idx8);
}

// merged pruned weight split for W2/W3/W4 (R12, 8 elems/thread).
__global__ void __launch_bounds__(256)
split_w_prune3_kernel(const float* __restrict__ s2,
                      const float* __restrict__ s3,
                      const float* __restrict__ s4,
                      __half* __restrict__ P2,
                      __half* __restrict__ P3,
                      __half* __restrict__ P4, size_t S)
{
    const int layer = blockIdx.y;
    const float* src = (layer == 0) ? s2 : (layer == 1) ? s3 : s4;
    __half* P = (layer == 0) ? P2 : (layer == 1) ? P3 : P4;
    size_t idx8 = (size_t)blockIdx.x * 256 + threadIdx.x;
    if (idx8 >= (size_t)NPRU * 512 / 8) return;
    size_t e = idx8 * 8;
    int row = (int)(e >> 9);
    int col = (int)(e & 511);
    int srow = (row < 512) ? row : row + 512;
    const float* s = src + (size_t)srow * 512 + col;
    float v[8];
    *(float4*)v = *(const float4*)s;
    *(float4*)(v + 4) = *(const float4*)(s + 4);
    split8_store(v, P, S, idx8);
}

__global__ void bias_pack_kernel(const float* bih1, const float* bhh1,
                                 const float* bih2, const float* bhh2,
                                 const float* bih3, const float* bhh3,
                                 const float* bih4, const float* bhh4,
                                 float* __restrict__ out)
{
    int i = blockIdx.x * 256 + threadIdx.x;
    if (i < 2048) {
        int sn = (i < 512) ? i : ((i < 1536) ? i + 512 : i - 1024);
        out[i] = bih1[sn] + bhh1[sn];
        return;
    }
    int j = i - 2048;
    if (j >= 3 * NPRU) return;
    int layer = j / NPRU;
    int n = j - layer * NPRU;
    int sn = (n < 512) ? n : n + 512;
    const float* bi = (layer == 0) ? bih2 : (layer == 1) ? bih3 : bih4;
    const float* bh = (layer == 0) ? bhh2 : (layer == 1) ? bhh3 : bhh4;
    out[i] = bi[sn] + bh[sn];
}

// ---- LSTM cell epilogues (R12, 4 elems/thread) ---------------------------------
__device__ __forceinline__ float sigm(float x) { return 1.0f / (1.0f + expf(-x)); }

union Pack4 { __half2 h[2]; uint2 v; };

__device__ __forceinline__ void split4_store(const float* v,
                                             __half* HP, size_t S,
                                             size_t idx4) {
    Pack4 p0, p1;
#pragma unroll
    for (int k = 0; k < 2; k++) {
        __half a0, a1, b0, b1;
        split2(v[2 * k], a0, a1);
        split2(v[2 * k + 1], b0, b1);
        p0.h[k].x = a0; p0.h[k].y = b0;
        p1.h[k].x = a1; p1.h[k].y = b1;
    }
    ((uint2*)HP)[idx4] = p0.v;
    ((uint2*)(HP + S))[idx4] = p1.v;
}

__global__ void cell_zero_kernel(const float* __restrict__ gates,
                                 int gstride, int goff, int ooff,
                                 __half* __restrict__ HP, size_t S,
                                 float* __restrict__ c)
{
    int idx4 = blockIdx.x * 256 + threadIdx.x;
    if (idx4 >= BATCH * HID / 4) return;
    int m = idx4 >> 7;
    int n = (idx4 & 127) << 2;
    const float* gr = gates + (size_t)m * gstride + n;
    float4 gi = *(const float4*)(gr);
    float4 gg = *(const float4*)(gr + goff);
    float4 go = *(const float4*)(gr + ooff);
    float hv[4], cv[4];
    const float* gip = &gi.x; const float* ggp = &gg.x; const float* gop = &go.x;
#pragma unroll
    for (int k = 0; k < 4; k++) {
        float cn = sigm(gip[k]) * tanhf(ggp[k]);
        hv[k] = fmaxf(sigm(gop[k]) * tanhf(cn), 0.f);
        cv[k] = fmaxf(cn, 0.f);
    }
    split4_store(hv, HP, S, idx4);
    if (c) *(float4*)(c + (size_t)idx4 * 4) = make_float4(cv[0], cv[1], cv[2], cv[3]);
}

// t=1 full step; G1 layout [i|g|o|f]: i+0, g+512, o+1024, f+1536
__global__ void cell_step_kernel(const float* __restrict__ gates,
                                 const float* __restrict__ cprev,
                                 __half* __restrict__ HP, size_t S)
{
    int idx4 = blockIdx.x * 256 + threadIdx.x;
    if (idx4 >= BATCH * HID / 4) return;
    int m = idx4 >> 7;
    int n = (idx4 & 127) << 2;
    const float* gr = gates + (size_t)m * G4 + n;
    float4 gi = *(const float4*)(gr);
    float4 gg = *(const float4*)(gr + 512);
    float4 go = *(const float4*)(gr + 1024);
    float4 gf = *(const float4*)(gr + 1536);
    float4 cp = *(const float4*)(cprev + (size_t)idx4 * 4);
    float hv[4];
    const float* gip = &gi.x; const float* gfp = &gf.x;
    const float* ggp = &gg.x; const float* gop = &go.x;
    const float* cpp = &cp.x;
#pragma unroll
    for (int k = 0; k < 4; k++) {
        float cn = sigm(gfp[k]) * cpp[k] + sigm(gip[k]) * tanhf(ggp[k]);
        hv[k] = fmaxf(sigm(gop[k]) * tanhf(cn), 0.f);
    }
    split4_store(hv, HP, S, idx4);
}

// ===========================================================================
// Merged-product HMMA GEMM, templated on BM, BN, SPLIT, NST.
//   <128,128,1,3>: big ragged GEMM — EXACT R12 body.
//   <128,256,0,2>: single-wave small GEMMs (Whh/layers/head), 2-stage.
// ===========================================================================
template <int BM, int BN, int SPLIT, int NST>
__global__ void __launch_bounds__(128, 2)
mma_gemm(const __half* __restrict__ Ap, size_t aPlane,
         const __half* __restrict__ Bp, size_t bPlane,
         float* __restrict__ C, float* __restrict__ C2,
         const float* __restrict__ bias,
         const float* __restrict__ U, float* __restrict__ Out,
         int M, int N, int K, int mode)
{
    constexpr int A_STG = BM * 128;
    constexpr int B_STG = BN * 128;
    constexpr int STG   = A_STG + B_STG;
    constexpr int AFRAG = BM / 32;
    constexpr int WROWS = BM / 2;
    constexpr int WCOLS = BN / 2;
    constexpr int JF    = BN / 16;     // b n8-fragments per warp

    extern __shared__ __align__(1024) char smem[];
    const uint32_t smb = smem_u32(smem);
    const int tid  = threadIdx.x;
    const int lane = tid & 31;
    const int wid  = tid >> 5;
    const int wm   = wid & 1;
    const int wn   = wid >> 1;

    int bm, bn;
    float* Cb;
    int ld, rowOff;
    if (SPLIT) {
        const int t = blockIdx.x;
        if (t < 768) { bm = (t / 12) * 128; bn = (t % 12) * 128; }
        else         { int u = t - 768; bm = 4096 + (u >> 2) * 128;
                       bn = 1536 + (u & 3) * 128; }
        if (bm < 4096) { Cb = C;  ld = 1536; rowOff = 0; }
        else           { Cb = C2; ld = 2048; rowOff = 4096; }
    } else {
        bm = blockIdx.y * BM;
        bn = blockIdx.x * BN;
        Cb = C; ld = N; rowOff = 0;
    }

    const __half* Abase = Ap + (size_t)bm * K;
    const __half* Bbase = Bp + (size_t)bn * K;

    const int NCH = K >> 5;

    const int lrow = tid >> 3;
    const int lcu  = tid & 7;
    const size_t aPl = (lcu < 4) ? 0 : aPlane;
    const size_t bPl = (lcu < 4) ? 0 : bPlane;
    const int kcol = (lcu & 3) * 8;

    auto issue = [&](int c) {
        if (c < NCH) {
            int k0 = c << 5;
            uint32_t sb = smb + (c % NST) * STG;
#pragma unroll
            for (int i = 0; i < BM / 16; i++) {
                int row = lrow + i * 16;
                uint32_t off = swz((uint32_t)(row * 128 + lcu * 16));
                cp16(sb + off, Abase + aPl + (size_t)row * K + k0 + kcol);
            }
#pragma unroll
            for (int i = 0; i < BN / 16; i++) {
                int row = lrow + i * 16;
                uint32_t off = swz((uint32_t)(row * 128 + lcu * 16));
                cp16(sb + A_STG + off, Bbase + bPl + (size_t)row * K + k0 + kcol);
            }
        }
        CP_COMMIT();
    };

    float acc[AFRAG][JF][4];
#pragma unroll
    for (int i = 0; i < AFRAG; i++)
#pragma unroll
        for (int j = 0; j < JF; j++)
#pragma unroll
            for (int v = 0; v < 4; v++) acc[i][j][v] = 0.f;

    issue(0);
    issue(1);

    const int a_row = wm * WROWS + (lane & 7) + ((lane >> 3) & 1) * 8;
    const int a_kb  = ((lane >> 4) & 1) * 16;
    const int b_row = wn * WCOLS + (lane & 7) + ((lane >> 4) & 1) * 8;
    const int b_kb  = ((lane >> 3) & 1) * 16;

    for (int c = 0; c < NCH; c++) {
        CP_WAIT1();
        __syncthreads();
        if (NST == 3) issue(c + 2);          // R12 order (3-stage)

        uint32_t sA = smb + (c % NST) * STG;
        uint32_t sB = sA + A_STG;

        if (BN == 128) {
            // ---- EXACT R12 inner body (protect the proven big-GEMM path) ----
#pragma unroll
            for (int ks = 0; ks < 2; ks++) {
                uint32_t a0[AFRAG][4], a1[AFRAG][4];
#pragma unroll
                for (int i = 0; i < AFRAG; i++) {
                    uint32_t base = (uint32_t)((a_row + i * 16) * 128 + ks * 32 + a_kb);
                    ldsm_x4(a0[i][0], a0[i][1], a0[i][2], a0[i][3], sA + swz(base));
                    ldsm_x4(a1[i][0], a1[i][1], a1[i][2], a1[i][3], sA + swz(base + 64));
                }
                uint32_t b0[JF][2], b1[JF][2];
#pragma unroll
                for (int j2 = 0; j2 < JF / 2; j2++) {
                    uint32_t base = (uint32_t)((b_row + j2 * 16) * 128 + ks * 32 + b_kb);
                    ldsm_x4(b0[2 * j2][0], b0[2 * j2][1], b0[2 * j2 + 1][0],
                            b0[2 * j2 + 1][1], sB + swz(base));
                    ldsm_x4(b1[2 * j2][0], b1[2 * j2][1], b1[2 * j2 + 1][0],
                            b1[2 * j2 + 1][1], sB + swz(base + 64));
                }
#pragma unroll
                for (int i = 0; i < AFRAG; i++)
#pragma unroll
                    for (int j = 0; j < JF; j++)
                        mma16816(acc[i][j], a0[i], b1[j]);
#pragma unroll
                for (int i = 0; i < AFRAG; i++)
#pragma unroll
                    for (int j = 0; j < JF; j++)
                        mma16816(acc[i][j], a1[i], b0[j]);
#pragma unroll
                for (int i = 0; i < AFRAG; i++)
#pragma unroll
                    for (int j = 0; j < JF; j++)
                        mma16816(acc[i][j], a0[i], b0[j]);
            }
        } else {
            // ---- BN=256 body: phase-local b-plane loads (lower reg pressure) ----
#pragma unroll
            for (int ks = 0; ks < 2; ks++) {
                uint32_t a0[AFRAG][4], a1[AFRAG][4];
#pragma unroll
                for (int i = 0; i < AFRAG; i++) {
                    uint32_t base = (uint32_t)((a_row + i * 16) * 128 + ks * 32 + a_kb);
                    ldsm_x4(a0[i][0], a0[i][1], a0[i][2], a0[i][3], sA + swz(base));
                    ldsm_x4(a1[i][0], a1[i][1], a1[i][2], a1[i][3], sA + swz(base + 64));
                }
                uint32_t bx[JF][2];
                // plane1 of B -> product a0*b1
#pragma unroll
                for (int j2 = 0; j2 < JF / 2; j2++) {
                    uint32_t base = (uint32_t)((b_row + j2 * 16) * 128 + ks * 32 + b_kb);
                    ldsm_x4(bx[2 * j2][0], bx[2 * j2][1], bx[2 * j2 + 1][0],
                            bx[2 * j2 + 1][1], sB + swz(base + 64));
                }
#pragma unroll
                for (int i = 0; i < AFRAG; i++)
#pragma unroll
                    for (int j = 0; j < JF; j++)
                        mma16816(acc[i][j], a0[i], bx[j]);
                // plane0 of B -> products a1*b0, a0*b0
#pragma unroll
                for (int j2 = 0; j2 < JF / 2; j2++) {
                    uint32_t base = (uint32_t)((b_row + j2 * 16) * 128 + ks * 32 + b_kb);
                    ldsm_x4(bx[2 * j2][0], bx[2 * j2][1], bx[2 * j2 + 1][0],
                            bx[2 * j2 + 1][1], sB + swz(base));
                }
#pragma unroll
                for (int i = 0; i < AFRAG; i++)
#pragma unroll
                    for (int j = 0; j < JF; j++)
                        mma16816(acc[i][j], a1[i], bx[j]);
#pragma unroll
                for (int i = 0; i < AFRAG; i++)
#pragma unroll
                    for (int j = 0; j < JF; j++)
                        mma16816(acc[i][j], a0[i], bx[j]);
            }
        }

        if (NST == 2) {                       // 2-stage: reload stage after use
            __syncthreads();
            issue(c + 2);
        }
    }

    // ---- epilogue ----
    const int r0    = bm + wm * WROWS + (lane >> 2);
    const int cbase = bn + wn * WCOLS + (lane & 3) * 2;

#pragma unroll
    for (int i = 0; i < AFRAG; i++) {
        const int rowA = r0 + i * 16;
        const int rowL = rowA - rowOff;
#pragma unroll
        for (int j = 0; j < JF; j++) {
            const int col = cbase + j * 8;
            float v0 = acc[i][j][0], v1 = acc[i][j][1];
            float v2 = acc[i][j][2], v3 = acc[i][j][3];
            if (mode == 0) {
                float b0 = bias[col], b1 = bias[col + 1];
                *(float2*)(Cb + (size_t)rowL * ld + col)       = make_float2(v0 + b0, v1 + b1);
                *(float2*)(Cb + (size_t)(rowL + 8) * ld + col) = make_float2(v2 + b0, v3 + b1);
            } else if (mode == 1) {
                float2* p0 = (float2*)(Cb + (size_t)rowL * ld + col);
                float2* p1 = (float2*)(Cb + (size_t)(rowL + 8) * ld + col);
                float2 o0 = *p0, o1 = *p1;
                *p0 = make_float2(o0.x + v0, o0.y + v1);
                *p1 = make_float2(o1.x + v2, o1.y + v3);
            } else {
                float b0 = bias[col], b1 = bias[col + 1];
                const float2 u0 = *(const float2*)(U + (size_t)rowL * ld + col);
                const float2 u1 = *(const float2*)(U + (size_t)(rowL + 8) * ld + col);
                float p00 = fmaxf(v0 + b0, 0.f), p01 = fmaxf(v1 + b1, 0.f);
                float p10 = fmaxf(v2 + b0, 0.f), p11 = fmaxf(v3 + b1, 0.f);
                *(float2*)(Out + (size_t)rowL * ld + col) =
                    make_float2(u0.x < p00 ? 1.f : 0.f, u0.y < p01 ? 1.f : 0.f);
                *(float2*)(Out + (size_t)(rowL + 8) * ld + col) =
                    make_float2(u1.x < p10 ? 1.f : 0.f, u1.y < p11 ? 1.f : 0.f);
            }
        }
    }
}

#define GS_BIG   (3 * (128 * 128 + 128 * 128))   // 98304
#define GS_SMALL (2 * (128 * 128 + 256 * 128))   // 98304

// ===========================================================================
extern "C" void kernel_launch(void* const* d_in, const int* in_sizes, int n_in,
                              void* d_out, int out_size)
{
    const float* state = (const float*)d_in[0];
    const float* goal  = (const float*)d_in[1];
    const float* u     = (const float*)d_in[2];
    const float* Wih1  = (const float*)d_in[3];
    const float* Whh1  = (const float*)d_in[4];
    const float* bih1  = (const float*)d_in[5];
    const float* bhh1  = (const float*)d_in[6];
    const float* Wih2  = (const float*)d_in[7];
    const float* bih2  = (const float*)d_in[9];
    const float* bhh2  = (const float*)d_in[10];
    const float* Wih3  = (const float*)d_in[11];
    const float* bih3  = (const float*)d_in[13];
    const float* bhh3  = (const float*)d_in[14];
    const float* Wih4  = (const float*)d_in[15];
    const float* bih4  = (const float*)d_in[17];
    const float* bhh4  = (const float*)d_in[18];
    const float* Wout  = (const float*)d_in[19];
    const float* bout  = (const float*)d_in[20];
    float* out = (float*)d_out;

    __half *XA, *W1, *Whh, *W2, *W3, *W4, *Wo, *Hs;
    float *G, *c1, *bias;
    cudaGetSymbolAddress((void**)&XA,  g_XA);
    cudaGetSymbolAddress((void**)&W1,  g_W1);
    cudaGetSymbolAddress((void**)&Whh, g_Whh);
    cudaGetSymbolAddress((void**)&W2,  g_W2);
    cudaGetSymbolAddress((void**)&W3,  g_W3);
    cudaGetSymbolAddress((void**)&W4,  g_W4);
    cudaGetSymbolAddress((void**)&Wo,  g_Wo);
    cudaGetSymbolAddress((void**)&Hs,  g_Hs);
    cudaGetSymbolAddress((void**)&G,   g_G);
    cudaGetSymbolAddress((void**)&c1,  g_c1);
    cudaGetSymbolAddress((void**)&bias, g_bias);

    cudaFuncSetAttribute(mma_gemm<128, 128, 1, 3>,
                         cudaFuncAttributeMaxDynamicSharedMemorySize, GS_BIG);
    cudaFuncSetAttribute(mma_gemm<128, 256, 0, 2>,
                         cudaFuncAttributeMaxDynamicSharedMemorySize, GS_SMALL);

    const size_t SX  = (size_t)8192 * 3072;
    const size_t SW1 = (size_t)2048 * 3072;
    const size_t SWs = (size_t)2048 * 512;
    const size_t SWp = (size_t)NPRU * 512;
    const size_t SWo = (size_t)512 * 512;
    const size_t SH  = (size_t)4096 * 512;
    float* G0 = G;                                   // 4096 x 1536 (t0 igo)
    float* G1 = G + (size_t)4096 * 1536;             // 4096 x 2048 (t1 igof)
    float* b1r = bias;
    float* b2p = bias + 2048;
    float* b3p = b2p + NPRU;
    float* b4p = b3p + NPRU;

    // ---- splits (R12 config) ----
    split_x_kernel<<<(int)(SX / 8 / 256), 256>>>(state, goal, XA, SX);
    split_w_map_kernel<<<(int)(SW1 / 8 / 256), 256>>>(Wih1, W1, SW1, 2048, 3072, 2);
    split_w_map_kernel<<<(int)(SWs / 8 / 256), 256>>>(Whh1, Whh, SWs, 2048, 512, 2);
    split_w_prune3_kernel<<<dim3((int)(SWp / 8 / 256), 3), 256>>>(
        Wih2, Wih3, Wih4, W2, W3, W4, SWp);
    split_w_map_kernel<<<(int)(SWo / 8 / 256), 256>>>(Wout, Wo, SWo, 512, 512, 0);
    bias_pack_kernel<<<(2048 + 3 * NPRU + 255) / 256, 256>>>(
        bih1, bhh1, bih2, bhh2, bih3, bhh3, bih4, bhh4, bias);

    // ---- big GEMM (ragged, R12): 768 igo tiles + 128 t1-f tiles ----
    mma_gemm<128, 128, 1, 3><<<896, 128, GS_BIG>>>(
        XA, SX, W1, SW1, G0, G1, b1r, nullptr, nullptr, 8192, 2048, 3072, 0);

    // cell1 @ t=0 (G0: [i|g|o], stride 1536)
    cell_zero_kernel<<<BATCH * HID / 4 / 256, 256>>>(G0, 1536, 512, 1024, Hs, SH, c1);

    // G1 += h1 @ Whh^T  ([i|g|o|f], N=2048) — single wave (256 CTAs)
    mma_gemm<128, 256, 0, 2><<<dim3(2048 / 256, 4096 / 128), 128, GS_SMALL>>>(
        Hs, SH, Whh, SWs, G1, nullptr, nullptr, nullptr, nullptr, 4096, 2048, 512, 1);

    // cell1 @ t=1 (G1: [i|g|o|f])
    cell_step_kernel<<<BATCH * HID / 4 / 256, 256>>>(G1, c1, Hs, SH);

    // ---- pruned layers (N=1536, [i|g|o]) — single wave (192 CTAs each) ----
    mma_gemm<128, 256, 0, 2><<<dim3(NPRU / 256, 4096 / 128), 128, GS_SMALL>>>(
        Hs, SH, W2, SWp, G0, nullptr, b2p, nullptr, nullptr, 4096, NPRU, 512, 0);
    cell_zero_kernel<<<BATCH * HID / 4 / 256, 256>>>(G0, NPRU, 512, 1024, Hs, SH, nullptr);

    mma_gemm<128, 256, 0, 2><<<dim3(NPRU / 256, 4096 / 128), 128, GS_SMALL>>>(
        Hs, SH, W3, SWp, G0, nullptr, b3p, nullptr, nullptr, 4096, NPRU, 512, 0);
    cell_zero_kernel<<<BATCH * HID / 4 / 256, 256>>>(G0, NPRU, 512, 1024, Hs, SH, nullptr);

    mma_gemm<128, 256, 0, 2><<<dim3(NPRU / 256, 4096 / 128), 128, GS_SMALL>>>(
        Hs, SH, W4, SWp, G0, nullptr, b4p, nullptr, nullptr, 4096, NPRU, 512, 0);
    cell_zero_kernel<<<BATCH * HID / 4 / 256, 256>>>(G0, NPRU, 512, 1024, Hs, SH, nullptr);

    // ---- head (64 CTAs): out = (u < relu(h4 @ Wout^T + bout)) ----
    mma_gemm<128, 256, 0, 2><<<dim3(512 / 256, 4096 / 128), 128, GS_SMALL>>>(
        Hs, SH, Wo, SWo, nullptr, nullptr, bout, u, out, 4096, 512, 512, 2);
}

// round 16
// speedup vs baseline: 1.4458x; 1.4458x over previous
#include <cuda_runtime.h>
#include <cuda_fp16.h>
#include <math.h>
#include <stdint.h>

// ===========================================================================
// Actor_10505490006716 — HMMA (mma.sync fp16) with 2-plane fp32 split.
// Round 16: exact R12 GEMM/cell path (best known, 1044.6us). All six
// preprocessing launches (split_x, split_W1, split_Whh, prune3, split_Wo,
// bias_pack) fused into ONE 17080-block kernel with region dispatch —
// per-thread work byte-identical to R12, one ramp/tail instead of six.
// ===========================================================================

#define BATCH 4096
#define HID   512
#define G4    2048
#define INDIM 3072
#define NPRU  1536

__device__ __half g_XA [(size_t)2 * 8192 * 3072];
__device__ __half g_W1 [(size_t)2 * 2048 * 3072];   // reordered [i|g|o|f]
__device__ __half g_Whh[(size_t)2 * 2048 * 512];    // reordered [i|g|o|f]
__device__ __half g_W2 [(size_t)2 * 1536 * 512];
__device__ __half g_W3 [(size_t)2 * 1536 * 512];
__device__ __half g_W4 [(size_t)2 * 1536 * 512];
__device__ __half g_Wo [(size_t)2 * 512 * 512];
__device__ __half g_Hs [(size_t)2 * 4096 * 512];
__device__ float g_G [(size_t)8192 * 2048];         // G0 (4096x1536) | G1 (4096x2048)
__device__ float g_c1[(size_t)4096 * 512];
__device__ float g_bias[2048 + 3 * 1536];           // b1r (igof) | b2p | b3p | b4p

// ---- PTX helpers ------------------------------------------------------------
__device__ __forceinline__ uint32_t smem_u32(const void* p) {
    uint32_t a;
    asm("{ .reg .u64 t; cvta.to.shared.u64 t, %1; cvt.u32.u64 %0, t; }"
        : "=r"(a) : "l"(p));
    return a;
}
__device__ __forceinline__ void cp16(uint32_t dst, const void* src) {
    asm volatile("cp.async.cg.shared.global [%0], [%1], 16;"
                 :: "r"(dst), "l"(src));
}
#define CP_COMMIT() asm volatile("cp.async.commit_group;" ::: "memory")
#define CP_WAIT1()  asm volatile("cp.async.wait_group 1;" ::: "memory")

__device__ __forceinline__ void ldsm_x4(uint32_t& r0, uint32_t& r1,
                                        uint32_t& r2, uint32_t& r3,
                                        uint32_t addr) {
    asm volatile("ldmatrix.sync.aligned.m8n8.x4.shared.b16 {%0,%1,%2,%3}, [%4];"
                 : "=r"(r0), "=r"(r1), "=r"(r2), "=r"(r3) : "r"(addr));
}
__device__ __forceinline__ void mma16816(float* d, const uint32_t* a,
                                         const uint32_t* b) {
    asm volatile("mma.sync.aligned.m16n8k16.row.col.f32.f16.f16.f32 "
                 "{%0,%1,%2,%3}, {%4,%5,%6,%7}, {%8,%9}, {%0,%1,%2,%3};"
                 : "+f"(d[0]), "+f"(d[1]), "+f"(d[2]), "+f"(d[3])
                 : "r"(a[0]), "r"(a[1]), "r"(a[2]), "r"(a[3]),
                   "r"(b[0]), "r"(b[1]));
}
__device__ __forceinline__ uint32_t swz(uint32_t off) {
    return off ^ ((off >> 3) & 0x70);
}

// ---- fp16 2-plane splitting ---------------------------------------------------
__device__ __forceinline__ void split2(float a, __half& o0, __half& o1) {
    __half b0 = __float2half_rn(a);
    o0 = b0;
    o1 = __float2half_rn(a - __half2float(b0));
}

union Pack8 { __half2 h[4]; uint4 v; };

__device__ __forceinline__ void split8_store(const float* v,
                                             __half* P, size_t S,
                                             size_t idx8) {
    Pack8 p0, p1;
#pragma unroll
    for (int k = 0; k < 4; k++) {
        __half a0, a1, b0, b1;
        split2(v[2 * k], a0, a1);
        split2(v[2 * k + 1], b0, b1);
        p0.h[k].x = a0; p0.h[k].y = b0;
        p1.h[k].x = a1; p1.h[k].y = b1;
    }
    ((uint4*)P)[idx8] = p0.v;
    ((uint4*)(P + S))[idx8] = p1.v;
}

__device__ __forceinline__ void split8_from(const float* s,
                                            __half* P, size_t S, size_t idx8) {
    float v[8];
    *(float4*)v = *(const float4*)s;
    *(float4*)(v + 4) = *(const float4*)(s + 4);
    split8_store(v, P, S, idx8);
}

// ===========================================================================
// Fused preprocessing: one grid, region dispatch. Per-thread work identical
// to R12's six kernels.
//   region 0: split_x      (12288 blocks)
//   region 1: split W1 map2 (3072 blocks)
//   region 2: split Whh map2 (512 blocks)
//   region 3: prune3 W2/3/4 (1152 blocks, 384 each)
//   region 4: split Wo      (128 blocks)
//   region 5: bias pack     (28 blocks)
// ===========================================================================
#define BX0 12288
#define BX1 (BX0 + 3072)
#define BX2 (BX1 + 512)
#define BX3 (BX2 + 1152)
#define BX4 (BX3 + 128)
#define BX5 (BX4 + 28)

__global__ void __launch_bounds__(256)
prep_all_kernel(const float* __restrict__ state, const float* __restrict__ goal,
                const float* __restrict__ Wih1, const float* __restrict__ Whh1,
                const float* __restrict__ Wih2, const float* __restrict__ Wih3,
                const float* __restrict__ Wih4, const float* __restrict__ Wout,
                const float* bih1, const float* bhh1,
                const float* bih2, const float* bhh2,
                const float* bih3, const float* bhh3,
                const float* bih4, const float* bhh4,
                __half* __restrict__ XA, __half* __restrict__ W1,
                __half* __restrict__ Whh, __half* __restrict__ W2,
                __half* __restrict__ W3, __half* __restrict__ W4,
                __half* __restrict__ Wo, float* __restrict__ bias)
{
    const int bid = blockIdx.x;
    const int tid = threadIdx.x;

    if (bid < BX0) {
        // ---- split_x: X = concat(state[:,t], goal[:,t]), 8 elems/thread ----
        const size_t SXp = (size_t)8192 * INDIM;
        size_t idx8 = (size_t)bid * 256 + tid;
        size_t e = idx8 * 8;
        int row = (int)(e / INDIM);
        int col = (int)(e % INDIM);
        int b = row & 4095, t = row >> 12;
        const float* src = (col < 2048)
            ? state + (size_t)(b * 4 + t) * 2048 + col
            : goal  + (size_t)(b * 4 + t) * 1024 + (col - 2048);
        split8_from(src, XA, SXp, idx8);
    } else if (bid < BX1) {
        // ---- W1 split, map2 [i|f|g|o] -> [i|g|o|f], K=3072 ----
        const size_t S = (size_t)2048 * 3072;
        size_t idx8 = (size_t)(bid - BX0) * 256 + tid;
        size_t e = idx8 * 8;
        int row = (int)(e / 3072);
        int col = (int)(e % 3072);
        int srow = (row < 512) ? row : ((row < 1536) ? row + 512 : row - 1024);
        split8_from(Wih1 + (size_t)srow * 3072 + col, W1, S, idx8);
    } else if (bid < BX2) {
        // ---- Whh split, map2, K=512 ----
        const size_t S = (size_t)2048 * 512;
        size_t idx8 = (size_t)(bid - BX1) * 256 + tid;
        size_t e = idx8 * 8;
        int row = (int)(e >> 9);
        int col = (int)(e & 511);
        int srow = (row < 512) ? row : ((row < 1536) ? row + 512 : row - 1024);
        split8_from(Whh1 + (size_t)srow * 512 + col, Whh, S, idx8);
    } else if (bid < BX3) {
        // ---- prune3: W2/W3/W4, out rows [i|g|o], src [i|f|g|o] ----
        const size_t S = (size_t)NPRU * 512;
        int rb = bid - BX2;
        int layer = rb / 384;
        const float* src = (layer == 0) ? Wih2 : (layer == 1) ? Wih3 : Wih4;
        __half* P = (layer == 0) ? W2 : (layer == 1) ? W3 : W4;
        size_t idx8 = (size_t)(rb - layer * 384) * 256 + tid;
        size_t e = idx8 * 8;
        int row = (int)(e >> 9);
        int col = (int)(e & 511);
        int srow = (row < 512) ? row : row + 512;
        split8_from(src + (size_t)srow * 512 + col, P, S, idx8);
    } else if (bid < BX4) {
        // ---- Wo split, identity, K=512 ----
        const size_t S = (size_t)512 * 512;
        size_t idx8 = (size_t)(bid - BX3) * 256 + tid;
        split8_from(Wout + idx8 * 8, Wo, S, idx8);
    } else {
        // ---- bias pack ----
        int i = (bid - BX4) * 256 + tid;
        if (i < 2048) {
            int sn = (i < 512) ? i : ((i < 1536) ? i + 512 : i - 1024);
            bias[i] = bih1[sn] + bhh1[sn];
            return;
        }
        int j = i - 2048;
        if (j >= 3 * NPRU) return;
        int layer = j / NPRU;
        int n = j - layer * NPRU;
        int sn = (n < 512) ? n : n + 512;
        const float* bi = (layer == 0) ? bih2 : (layer == 1) ? bih3 : bih4;
        const float* bh = (layer == 0) ? bhh2 : (layer == 1) ? bhh3 : bhh4;
        bias[i] = bi[sn] + bh[sn];
    }
}

// ---- LSTM cell epilogues (R12, 4 elems/thread) ---------------------------------
__device__ __forceinline__ float sigm(float x) { return 1.0f / (1.0f + expf(-x)); }

union Pack4 { __half2 h[2]; uint2 v; };

__device__ __forceinline__ void split4_store(const float* v,
                                             __half* HP, size_t S,
                                             size_t idx4) {
    Pack4 p0, p1;
#pragma unroll
    for (int k = 0; k < 2; k++) {
        __half a0, a1, b0, b1;
        split2(v[2 * k], a0, a1);
        split2(v[2 * k + 1], b0, b1);
        p0.h[k].x = a0; p0.h[k].y = b0;
        p1.h[k].x = a1; p1.h[k].y = b1;
    }
    ((uint2*)HP)[idx4] = p0.v;
    ((uint2*)(HP + S))[idx4] = p1.v;
}

__global__ void cell_zero_kernel(const float* __restrict__ gates,
                                 int gstride, int goff, int ooff,
                                 __half* __restrict__ HP, size_t S,
                                 float* __restrict__ c)
{
    int idx4 = blockIdx.x * 256 + threadIdx.x;
    if (idx4 >= BATCH * HID / 4) return;
    int m = idx4 >> 7;
    int n = (idx4 & 127) << 2;
    const float* gr = gates + (size_t)m * gstride + n;
    float4 gi = *(const float4*)(gr);
    float4 gg = *(const float4*)(gr + goff);
    float4 go = *(const float4*)(gr + ooff);
    float hv[4], cv[4];
    const float* gip = &gi.x; const float* ggp = &gg.x; const float* gop = &go.x;
#pragma unroll
    for (int k = 0; k < 4; k++) {
        float cn = sigm(gip[k]) * tanhf(ggp[k]);
        hv[k] = fmaxf(sigm(gop[k]) * tanhf(cn), 0.f);
        cv[k] = fmaxf(cn, 0.f);
    }
    split4_store(hv, HP, S, idx4);
    if (c) *(float4*)(c + (size_t)idx4 * 4) = make_float4(cv[0], cv[1], cv[2], cv[3]);
}

// t=1 full step; G1 layout [i|g|o|f]
__global__ void cell_step_kernel(const float* __restrict__ gates,
                                 const float* __restrict__ cprev,
                                 __half* __restrict__ HP, size_t S)
{
    int idx4 = blockIdx.x * 256 + threadIdx.x;
    if (idx4 >= BATCH * HID / 4) return;
    int m = idx4 >> 7;
    int n = (idx4 & 127) << 2;
    const float* gr = gates + (size_t)m * G4 + n;
    float4 gi = *(const float4*)(gr);
    float4 gg = *(const float4*)(gr + 512);
    float4 go = *(const float4*)(gr + 1024);
    float4 gf = *(const float4*)(gr + 1536);
    float4 cp = *(const float4*)(cprev + (size_t)idx4 * 4);
    float hv[4];
    const float* gip = &gi.x; const float* gfp = &gf.x;
    const float* ggp = &gg.x; const float* gop = &go.x;
    const float* cpp = &cp.x;
#pragma unroll
    for (int k = 0; k < 4; k++) {
        float cn = sigm(gfp[k]) * cpp[k] + sigm(gip[k]) * tanhf(ggp[k]);
        hv[k] = fmaxf(sigm(gop[k]) * tanhf(cn), 0.f);
    }
    split4_store(hv, HP, S, idx4);
}

// ===========================================================================
// Merged-product HMMA GEMM (EXACT R12).
// ===========================================================================
#define NSTAGE 3

template <int BM, int SPLIT>
__global__ void __launch_bounds__(128, (BM == 128 ? 2 : 3))
mma_gemm(const __half* __restrict__ Ap, size_t aPlane,
         const __half* __restrict__ Bp, size_t bPlane,
         float* __restrict__ C, float* __restrict__ C2,
         const float* __restrict__ bias,
         const float* __restrict__ U, float* __restrict__ Out,
         int M, int N, int K, int mode)
{
    constexpr int A_STG = BM * 128;
    constexpr int STG   = A_STG + 16384;
    constexpr int AFRAG = BM / 32;
    constexpr int WROWS = BM / 2;

    extern __shared__ __align__(1024) char smem[];
    const uint32_t smb = smem_u32(smem);
    const int tid  = threadIdx.x;
    const int lane = tid & 31;
    const int wid  = tid >> 5;
    const int wm   = wid & 1;
    const int wn   = wid >> 1;

    int bm, bn;
    float* Cb;
    int ld, rowOff;
    if (SPLIT) {
        const int t = blockIdx.x;
        if (t < 768) { bm = (t / 12) * 128; bn = (t % 12) * 128; }
        else         { int u = t - 768; bm = 4096 + (u >> 2) * 128;
                       bn = 1536 + (u & 3) * 128; }
        if (bm < 4096) { Cb = C;  ld = 1536; rowOff = 0; }
        else           { Cb = C2; ld = 2048; rowOff = 4096; }
    } else {
        bm = blockIdx.y * BM;
        bn = blockIdx.x * 128;
        Cb = C; ld = N; rowOff = 0;
    }

    const __half* Abase = Ap + (size_t)bm * K;
    const __half* Bbase = Bp + (size_t)bn * K;

    const int NCH = K >> 5;

    const int lrow = tid >> 3;
    const int lcu  = tid & 7;
    const size_t aPl = (lcu < 4) ? 0 : aPlane;
    const size_t bPl = (lcu < 4) ? 0 : bPlane;
    const int kcol = (lcu & 3) * 8;

    auto issue = [&](int c) {
        if (c < NCH) {
            int k0 = c << 5;
            uint32_t sb = smb + (c % NSTAGE) * STG;
#pragma unroll
            for (int i = 0; i < BM / 16; i++) {
                int row = lrow + i * 16;
                uint32_t off = swz((uint32_t)(row * 128 + lcu * 16));
                cp16(sb + off, Abase + aPl + (size_t)row * K + k0 + kcol);
            }
#pragma unroll
            for (int i = 0; i < 8; i++) {
                int row = lrow + i * 16;
                uint32_t off = swz((uint32_t)(row * 128 + lcu * 16));
                cp16(sb + A_STG + off, Bbase + bPl + (size_t)row * K + k0 + kcol);
            }
        }
        CP_COMMIT();
    };

    float acc[AFRAG][8][4];
#pragma unroll
    for (int i = 0; i < AFRAG; i++)
#pragma unroll
        for (int j = 0; j < 8; j++)
#pragma unroll
            for (int v = 0; v < 4; v++) acc[i][j][v] = 0.f;

    issue(0);
    issue(1);

    const int a_row = wm * WROWS + (lane & 7) + ((lane >> 3) & 1) * 8;
    const int a_kb  = ((lane >> 4) & 1) * 16;
    const int b_row = wn * 64 + (lane & 7) + ((lane >> 4) & 1) * 8;
    const int b_kb  = ((lane >> 3) & 1) * 16;

    for (int c = 0; c < NCH; c++) {
        CP_WAIT1();
        __syncthreads();
        issue(c + 2);

        uint32_t sA = smb + (c % NSTAGE) * STG;
        uint32_t sB = sA + A_STG;

#pragma unroll
        for (int ks = 0; ks < 2; ks++) {
            uint32_t a0[AFRAG][4], a1[AFRAG][4];
#pragma unroll
            for (int i = 0; i < AFRAG; i++) {
                uint32_t base = (uint32_t)((a_row + i * 16) * 128 + ks * 32 + a_kb);
                ldsm_x4(a0[i][0], a0[i][1], a0[i][2], a0[i][3], sA + swz(base));
                ldsm_x4(a1[i][0], a1[i][1], a1[i][2], a1[i][3], sA + swz(base + 64));
            }
            uint32_t b0[8][2], b1[8][2];
#pragma unroll
            for (int j2 = 0; j2 < 4; j2++) {
                uint32_t base = (uint32_t)((b_row + j2 * 16) * 128 + ks * 32 + b_kb);
                ldsm_x4(b0[2 * j2][0], b0[2 * j2][1], b0[2 * j2 + 1][0],
                        b0[2 * j2 + 1][1], sB + swz(base));
                ldsm_x4(b1[2 * j2][0], b1[2 * j2][1], b1[2 * j2 + 1][0],
                        b1[2 * j2 + 1][1], sB + swz(base + 64));
            }
#pragma unroll
            for (int i = 0; i < AFRAG; i++)
#pragma unroll
                for (int j = 0; j < 8; j++)
                    mma16816(acc[i][j], a0[i], b1[j]);
#pragma unroll
            for (int i = 0; i < AFRAG; i++)
#pragma unroll
                for (int j = 0; j < 8; j++)
                    mma16816(acc[i][j], a1[i], b0[j]);
#pragma unroll
            for (int i = 0; i < AFRAG; i++)
#pragma unroll
                for (int j = 0; j < 8; j++)
                    mma16816(acc[i][j], a0[i], b0[j]);
        }
    }

    // ---- epilogue ----
    const int r0    = bm + wm * WROWS + (lane >> 2);
    const int cbase = bn + wn * 64 + (lane & 3) * 2;

#pragma unroll
    for (int i = 0; i < AFRAG; i++) {
        const int rowA = r0 + i * 16;
        const int rowL = rowA - rowOff;
#pragma unroll
        for (int j = 0; j < 8; j++) {
            const int col = cbase + j * 8;
            float v0 = acc[i][j][0], v1 = acc[i][j][1];
            float v2 = acc[i][j][2], v3 = acc[i][j][3];
            if (mode == 0) {
                float b0 = bias[col], b1 = bias[col + 1];
                *(float2*)(Cb + (size_t)rowL * ld + col)       = make_float2(v0 + b0, v1 + b1);
                *(float2*)(Cb + (size_t)(rowL + 8) * ld + col) = make_float2(v2 + b0, v3 + b1);
            } else if (mode == 1) {
                float2* p0 = (float2*)(Cb + (size_t)rowL * ld + col);
                float2* p1 = (float2*)(Cb + (size_t)(rowL + 8) * ld + col);
                float2 o0 = *p0, o1 = *p1;
                *p0 = make_float2(o0.x + v0, o0.y + v1);
                *p1 = make_float2(o1.x + v2, o1.y + v3);
            } else {
                float b0 = bias[col], b1 = bias[col + 1];
                const float2 u0 = *(const float2*)(U + (size_t)rowL * ld + col);
                const float2 u1 = *(const float2*)(U + (size_t)(rowL + 8) * ld + col);
                float p00 = fmaxf(v0 + b0, 0.f), p01 = fmaxf(v1 + b1, 0.f);
                float p10 = fmaxf(v2 + b0, 0.f), p11 = fmaxf(v3 + b1, 0.f);
                *(float2*)(Out + (size_t)rowL * ld + col) =
                    make_float2(u0.x < p00 ? 1.f : 0.f, u0.y < p01 ? 1.f : 0.f);
                *(float2*)(Out + (size_t)(rowL + 8) * ld + col) =
                    make_float2(u1.x < p10 ? 1.f : 0.f, u1.y < p11 ? 1.f : 0.f);
            }
        }
    }
}

#define GSMEM128 (NSTAGE * (128 * 128 + 16384))   // 98304
#define GSMEM64  (NSTAGE * (64 * 128 + 16384))    // 73728

// ===========================================================================
extern "C" void kernel_launch(void* const* d_in, const int* in_sizes, int n_in,
                              void* d_out, int out_size)
{
    const float* state = (const float*)d_in[0];
    const float* goal  = (const float*)d_in[1];
    const float* u     = (const float*)d_in[2];
    const float* Wih1  = (const float*)d_in[3];
    const float* Whh1  = (const float*)d_in[4];
    const float* bih1  = (const float*)d_in[5];
    const float* bhh1  = (const float*)d_in[6];
    const float* Wih2  = (const float*)d_in[7];
    const float* bih2  = (const float*)d_in[9];
    const float* bhh2  = (const float*)d_in[10];
    const float* Wih3  = (const float*)d_in[11];
    const float* bih3  = (const float*)d_in[13];
    const float* bhh3  = (const float*)d_in[14];
    const float* Wih4  = (const float*)d_in[15];
    const float* bih4  = (const float*)d_in[17];
    const float* bhh4  = (const float*)d_in[18];
    const float* Wout  = (const float*)d_in[19];
    const float* bout  = (const float*)d_in[20];
    float* out = (float*)d_out;

    __half *XA, *W1, *Whh, *W2, *W3, *W4, *Wo, *Hs;
    float *G, *c1, *bias;
    cudaGetSymbolAddress((void**)&XA,  g_XA);
    cudaGetSymbolAddress((void**)&W1,  g_W1);
    cudaGetSymbolAddress((void**)&Whh, g_Whh);
    cudaGetSymbolAddress((void**)&W2,  g_W2);
    cudaGetSymbolAddress((void**)&W3,  g_W3);
    cudaGetSymbolAddress((void**)&W4,  g_W4);
    cudaGetSymbolAddress((void**)&Wo,  g_Wo);
    cudaGetSymbolAddress((void**)&Hs,  g_Hs);
    cudaGetSymbolAddress((void**)&G,   g_G);
    cudaGetSymbolAddress((void**)&c1,  g_c1);
    cudaGetSymbolAddress((void**)&bias, g_bias);

    cudaFuncSetAttribute(mma_gemm<128, 1>,
                         cudaFuncAttributeMaxDynamicSharedMemorySize, GSMEM128);
    cudaFuncSetAttribute(mma_gemm<128, 0>,
                         cudaFuncAttributeMaxDynamicSharedMemorySize, GSMEM128);
    cudaFuncSetAttribute(mma_gemm<64, 0>,
                         cudaFuncAttributeMaxDynamicSharedMemorySize, GSMEM64);

    const size_t SX  = (size_t)8192 * 3072;
    const size_t SWs = (size_t)2048 * 512;
    const size_t SWp = (size_t)NPRU * 512;
    const size_t SH  = (size_t)4096 * 512;
    float* G0 = G;                                   // 4096 x 1536 (t0 igo)
    float* G1 = G + (size_t)4096 * 1536;             // 4096 x 2048 (t1 igof)
    float* b1r = bias;
    float* b2p = bias + 2048;
    float* b3p = b2p + NPRU;
    float* b4p = b3p + NPRU;

    // ---- fused preprocessing (one launch, 17080 blocks) ----
    prep_all_kernel<<<BX5, 256>>>(
        state, goal, Wih1, Whh1, Wih2, Wih3, Wih4, Wout,
        bih1, bhh1, bih2, bhh2, bih3, bhh3, bih4, bhh4,
        XA, W1, Whh, W2, W3, W4, Wo, bias);

    // ---- big GEMM (ragged, R12): 768 igo tiles + 128 t1-f tiles ----
    mma_gemm<128, 1><<<896, 128, GSMEM128>>>(
        XA, SX, W1, (size_t)2048 * 3072, G0, G1, b1r, nullptr, nullptr,
        8192, 2048, 3072, 0);

    // cell1 @ t=0 (G0: [i|g|o], stride 1536)
    cell_zero_kernel<<<BATCH * HID / 4 / 256, 256>>>(G0, 1536, 512, 1024, Hs, SH, c1);

    // G1 += h1 @ Whh^T  ([i|g|o|f], N=2048)
    mma_gemm<128, 0><<<dim3(2048 / 128, 4096 / 128), 128, GSMEM128>>>(
        Hs, SH, Whh, SWs, G1, nullptr, nullptr, nullptr, nullptr,
        4096, 2048, 512, 1);

    // cell1 @ t=1 (G1: [i|g|o|f])
    cell_step_kernel<<<BATCH * HID / 4 / 256, 256>>>(G1, c1, Hs, SH);

    // ---- pruned layers (N=1536, [i|g|o]) on BM=64 (R12) ----
    mma_gemm<64, 0><<<dim3(NPRU / 128, 4096 / 64), 128, GSMEM64>>>(
        Hs, SH, W2, SWp, G0, nullptr, b2p, nullptr, nullptr, 4096, NPRU, 512, 0);
    cell_zero_kernel<<<BATCH * HID / 4 / 256, 256>>>(G0, NPRU, 512, 1024, Hs, SH, nullptr);

    mma_gemm<64, 0><<<dim3(NPRU / 128, 4096 / 64), 128, GSMEM64>>>(
        Hs, SH, W3, SWp, G0, nullptr, b3p, nullptr, nullptr, 4096, NPRU, 512, 0);
    cell_zero_kernel<<<BATCH * HID / 4 / 256, 256>>>(G0, NPRU, 512, 1024, Hs, SH, nullptr);

    mma_gemm<64, 0><<<dim3(NPRU / 128, 4096 / 64), 128, GSMEM64>>>(
        Hs, SH, W4, SWp, G0, nullptr, b4p, nullptr, nullptr, 4096, NPRU, 512, 0);
    cell_zero_kernel<<<BATCH * HID / 4 / 256, 256>>>(G0, NPRU, 512, 1024, Hs, SH, nullptr);

    // ---- head: out = (u < relu(h4 @ Wout^T + bout)) ----
    mma_gemm<64, 0><<<dim3(512 / 128, 4096 / 64), 128, GSMEM64>>>(
        Hs, SH, Wo, (size_t)512 * 512, nullptr, nullptr, bout, u, out,
        4096, 512, 512, 2);
}

// round 17
// speedup vs baseline: 1.4742x; 1.0196x over previous
#include <cuda_runtime.h>
#include <cuda_fp16.h>
#include <math.h>
#include <stdint.h>

// ===========================================================================
// Actor_10505490006716 — HMMA (mma.sync fp16) with 2-plane fp32 split.
// Round 17: R16 (best known) with ONE change backed by ncu: the Whh GEMM
// moves from BM=128 (regs=255, occ 10.8%, tensor 44%, 98us) to the proven
// BM=64 template (3 CTAs/SM, 12 warps) that the layer GEMMs showed runs
// ~1.6x higher throughput in this short-K latency-bound regime.
// ===========================================================================

#define BATCH 4096
#define HID   512
#define G4    2048
#define INDIM 3072
#define NPRU  1536

__device__ __half g_XA [(size_t)2 * 8192 * 3072];
__device__ __half g_W1 [(size_t)2 * 2048 * 3072];   // reordered [i|g|o|f]
__device__ __half g_Whh[(size_t)2 * 2048 * 512];    // reordered [i|g|o|f]
__device__ __half g_W2 [(size_t)2 * 1536 * 512];
__device__ __half g_W3 [(size_t)2 * 1536 * 512];
__device__ __half g_W4 [(size_t)2 * 1536 * 512];
__device__ __half g_Wo [(size_t)2 * 512 * 512];
__device__ __half g_Hs [(size_t)2 * 4096 * 512];
__device__ float g_G [(size_t)8192 * 2048];         // G0 (4096x1536) | G1 (4096x2048)
__device__ float g_c1[(size_t)4096 * 512];
__device__ float g_bias[2048 + 3 * 1536];           // b1r (igof) | b2p | b3p | b4p

// ---- PTX helpers ------------------------------------------------------------
__device__ __forceinline__ uint32_t smem_u32(const void* p) {
    uint32_t a;
    asm("{ .reg .u64 t; cvta.to.shared.u64 t, %1; cvt.u32.u64 %0, t; }"
        : "=r"(a) : "l"(p));
    return a;
}
__device__ __forceinline__ void cp16(uint32_t dst, const void* src) {
    asm volatile("cp.async.cg.shared.global [%0], [%1], 16;"
                 :: "r"(dst), "l"(src));
}
#define CP_COMMIT() asm volatile("cp.async.commit_group;" ::: "memory")
#define CP_WAIT1()  asm volatile("cp.async.wait_group 1;" ::: "memory")

__device__ __forceinline__ void ldsm_x4(uint32_t& r0, uint32_t& r1,
                                        uint32_t& r2, uint32_t& r3,
                                        uint32_t addr) {
    asm volatile("ldmatrix.sync.aligned.m8n8.x4.shared.b16 {%0,%1,%2,%3}, [%4];"
                 : "=r"(r0), "=r"(r1), "=r"(r2), "=r"(r3) : "r"(addr));
}
__device__ __forceinline__ void mma16816(float* d, const uint32_t* a,
                                         const uint32_t* b) {
    asm volatile("mma.sync.aligned.m16n8k16.row.col.f32.f16.f16.f32 "
                 "{%0,%1,%2,%3}, {%4,%5,%6,%7}, {%8,%9}, {%0,%1,%2,%3};"
                 : "+f"(d[0]), "+f"(d[1]), "+f"(d[2]), "+f"(d[3])
                 : "r"(a[0]), "r"(a[1]), "r"(a[2]), "r"(a[3]),
                   "r"(b[0]), "r"(b[1]));
}
__device__ __forceinline__ uint32_t swz(uint32_t off) {
    return off ^ ((off >> 3) & 0x70);
}

// ---- fp16 2-plane splitting ---------------------------------------------------
__device__ __forceinline__ void split2(float a, __half& o0, __half& o1) {
    __half b0 = __float2half_rn(a);
    o0 = b0;
    o1 = __float2half_rn(a - __half2float(b0));
}

union Pack8 { __half2 h[4]; uint4 v; };

__device__ __forceinline__ void split8_store(const float* v,
                                             __half* P, size_t S,
                                             size_t idx8) {
    Pack8 p0, p1;
#pragma unroll
    for (int k = 0; k < 4; k++) {
        __half a0, a1, b0, b1;
        split2(v[2 * k], a0, a1);
        split2(v[2 * k + 1], b0, b1);
        p0.h[k].x = a0; p0.h[k].y = b0;
        p1.h[k].x = a1; p1.h[k].y = b1;
    }
    ((uint4*)P)[idx8] = p0.v;
    ((uint4*)(P + S))[idx8] = p1.v;
}

__device__ __forceinline__ void split8_from(const float* s,
                                            __half* P, size_t S, size_t idx8) {
    float v[8];
    *(float4*)v = *(const float4*)s;
    *(float4*)(v + 4) = *(const float4*)(s + 4);
    split8_store(v, P, S, idx8);
}

// ===========================================================================
// Fused preprocessing: one grid, region dispatch (R16).
// ===========================================================================
#define BX0 12288
#define BX1 (BX0 + 3072)
#define BX2 (BX1 + 512)
#define BX3 (BX2 + 1152)
#define BX4 (BX3 + 128)
#define BX5 (BX4 + 28)

__global__ void __launch_bounds__(256)
prep_all_kernel(const float* __restrict__ state, const float* __restrict__ goal,
                const float* __restrict__ Wih1, const float* __restrict__ Whh1,
                const float* __restrict__ Wih2, const float* __restrict__ Wih3,
                const float* __restrict__ Wih4, const float* __restrict__ Wout,
                const float* bih1, const float* bhh1,
                const float* bih2, const float* bhh2,
                const float* bih3, const float* bhh3,
                const float* bih4, const float* bhh4,
                __half* __restrict__ XA, __half* __restrict__ W1,
                __half* __restrict__ Whh, __half* __restrict__ W2,
                __half* __restrict__ W3, __half* __restrict__ W4,
                __half* __restrict__ Wo, float* __restrict__ bias)
{
    const int bid = blockIdx.x;
    const int tid = threadIdx.x;

    if (bid < BX0) {
        const size_t SXp = (size_t)8192 * INDIM;
        size_t idx8 = (size_t)bid * 256 + tid;
        size_t e = idx8 * 8;
        int row = (int)(e / INDIM);
        int col = (int)(e % INDIM);
        int b = row & 4095, t = row >> 12;
        const float* src = (col < 2048)
            ? state + (size_t)(b * 4 + t) * 2048 + col
            : goal  + (size_t)(b * 4 + t) * 1024 + (col - 2048);
        split8_from(src, XA, SXp, idx8);
    } else if (bid < BX1) {
        const size_t S = (size_t)2048 * 3072;
        size_t idx8 = (size_t)(bid - BX0) * 256 + tid;
        size_t e = idx8 * 8;
        int row = (int)(e / 3072);
        int col = (int)(e % 3072);
        int srow = (row < 512) ? row : ((row < 1536) ? row + 512 : row - 1024);
        split8_from(Wih1 + (size_t)srow * 3072 + col, W1, S, idx8);
    } else if (bid < BX2) {
        const size_t S = (size_t)2048 * 512;
        size_t idx8 = (size_t)(bid - BX1) * 256 + tid;
        size_t e = idx8 * 8;
        int row = (int)(e >> 9);
        int col = (int)(e & 511);
        int srow = (row < 512) ? row : ((row < 1536) ? row + 512 : row - 1024);
        split8_from(Whh1 + (size_t)srow * 512 + col, Whh, S, idx8);
    } else if (bid < BX3) {
        const size_t S = (size_t)NPRU * 512;
        int rb = bid - BX2;
        int layer = rb / 384;
        const float* src = (layer == 0) ? Wih2 : (layer == 1) ? Wih3 : Wih4;
        __half* P = (layer == 0) ? W2 : (layer == 1) ? W3 : W4;
        size_t idx8 = (size_t)(rb - layer * 384) * 256 + tid;
        size_t e = idx8 * 8;
        int row = (int)(e >> 9);
        int col = (int)(e & 511);
        int srow = (row < 512) ? row : row + 512;
        split8_from(src + (size_t)srow * 512 + col, P, S, idx8);
    } else if (bid < BX4) {
        const size_t S = (size_t)512 * 512;
        size_t idx8 = (size_t)(bid - BX3) * 256 + tid;
        split8_from(Wout + idx8 * 8, Wo, S, idx8);
    } else {
        int i = (bid - BX4) * 256 + tid;
        if (i < 2048) {
            int sn = (i < 512) ? i : ((i < 1536) ? i + 512 : i - 1024);
            bias[i] = bih1[sn] + bhh1[sn];
            return;
        }
        int j = i - 2048;
        if (j >= 3 * NPRU) return;
        int layer = j / NPRU;
        int n = j - layer * NPRU;
        int sn = (n < 512) ? n : n + 512;
        const float* bi = (layer == 0) ? bih2 : (layer == 1) ? bih3 : bih4;
        const float* bh = (layer == 0) ? bhh2 : (layer == 1) ? bhh3 : bhh4;
        bias[i] = bi[sn] + bh[sn];
    }
}

// ---- LSTM cell epilogues (R12, 4 elems/thread) ---------------------------------
__device__ __forceinline__ float sigm(float x) { return 1.0f / (1.0f + expf(-x)); }

union Pack4 { __half2 h[2]; uint2 v; };

__device__ __forceinline__ void split4_store(const float* v,
                                             __half* HP, size_t S,
                                             size_t idx4) {
    Pack4 p0, p1;
#pragma unroll
    for (int k = 0; k < 2; k++) {
        __half a0, a1, b0, b1;
        split2(v[2 * k], a0, a1);
        split2(v[2 * k + 1], b0, b1);
        p0.h[k].x = a0; p0.h[k].y = b0;
        p1.h[k].x = a1; p1.h[k].y = b1;
    }
    ((uint2*)HP)[idx4] = p0.v;
    ((uint2*)(HP + S))[idx4] = p1.v;
}

__global__ void cell_zero_kernel(const float* __restrict__ gates,
                                 int gstride, int goff, int ooff,
                                 __half* __restrict__ HP, size_t S,
                                 float* __restrict__ c)
{
    int idx4 = blockIdx.x * 256 + threadIdx.x;
    if (idx4 >= BATCH * HID / 4) return;
    int m = idx4 >> 7;
    int n = (idx4 & 127) << 2;
    const float* gr = gates + (size_t)m * gstride + n;
    float4 gi = *(const float4*)(gr);
    float4 gg = *(const float4*)(gr + goff);
    float4 go = *(const float4*)(gr + ooff);
    float hv[4], cv[4];
    const float* gip = &gi.x; const float* ggp = &gg.x; const float* gop = &go.x;
#pragma unroll
    for (int k = 0; k < 4; k++) {
        float cn = sigm(gip[k]) * tanhf(ggp[k]);
        hv[k] = fmaxf(sigm(gop[k]) * tanhf(cn), 0.f);
        cv[k] = fmaxf(cn, 0.f);
    }
    split4_store(hv, HP, S, idx4);
    if (c) *(float4*)(c + (size_t)idx4 * 4) = make_float4(cv[0], cv[1], cv[2], cv[3]);
}

// t=1 full step; G1 layout [i|g|o|f]
__global__ void cell_step_kernel(const float* __restrict__ gates,
                                 const float* __restrict__ cprev,
                                 __half* __restrict__ HP, size_t S)
{
    int idx4 = blockIdx.x * 256 + threadIdx.x;
    if (idx4 >= BATCH * HID / 4) return;
    int m = idx4 >> 7;
    int n = (idx4 & 127) << 2;
    const float* gr = gates + (size_t)m * G4 + n;
    float4 gi = *(const float4*)(gr);
    float4 gg = *(const float4*)(gr + 512);
    float4 go = *(const float4*)(gr + 1024);
    float4 gf = *(const float4*)(gr + 1536);
    float4 cp = *(const float4*)(cprev + (size_t)idx4 * 4);
    float hv[4];
    const float* gip = &gi.x; const float* gfp = &gf.x;
    const float* ggp = &gg.x; const float* gop = &go.x;
    const float* cpp = &cp.x;
#pragma unroll
    for (int k = 0; k < 4; k++) {
        float cn = sigm(gfp[k]) * cpp[k] + sigm(gip[k]) * tanhf(ggp[k]);
        hv[k] = fmaxf(sigm(gop[k]) * tanhf(cn), 0.f);
    }
    split4_store(hv, HP, S, idx4);
}

// ===========================================================================
// Merged-product HMMA GEMM (EXACT R12).
// ===========================================================================
#define NSTAGE 3

template <int BM, int SPLIT>
__global__ void __launch_bounds__(128, (BM == 128 ? 2 : 3))
mma_gemm(const __half* __restrict__ Ap, size_t aPlane,
         const __half* __restrict__ Bp, size_t bPlane,
         float* __restrict__ C, float* __restrict__ C2,
         const float* __restrict__ bias,
         const float* __restrict__ U, float* __restrict__ Out,
         int M, int N, int K, int mode)
{
    constexpr int A_STG = BM * 128;
    constexpr int STG   = A_STG + 16384;
    constexpr int AFRAG = BM / 32;
    constexpr int WROWS = BM / 2;

    extern __shared__ __align__(1024) char smem[];
    const uint32_t smb = smem_u32(smem);
    const int tid  = threadIdx.x;
    const int lane = tid & 31;
    const int wid  = tid >> 5;
    const int wm   = wid & 1;
    const int wn   = wid >> 1;

    int bm, bn;
    float* Cb;
    int ld, rowOff;
    if (SPLIT) {
        const int t = blockIdx.x;
        if (t < 768) { bm = (t / 12) * 128; bn = (t % 12) * 128; }
        else         { int u = t - 768; bm = 4096 + (u >> 2) * 128;
                       bn = 1536 + (u & 3) * 128; }
        if (bm < 4096) { Cb = C;  ld = 1536; rowOff = 0; }
        else           { Cb = C2; ld = 2048; rowOff = 4096; }
    } else {
        bm = blockIdx.y * BM;
        bn = blockIdx.x * 128;
        Cb = C; ld = N; rowOff = 0;
    }

    const __half* Abase = Ap + (size_t)bm * K;
    const __half* Bbase = Bp + (size_t)bn * K;

    const int NCH = K >> 5;

    const int lrow = tid >> 3;
    const int lcu  = tid & 7;
    const size_t aPl = (lcu < 4) ? 0 : aPlane;
    const size_t bPl = (lcu < 4) ? 0 : bPlane;
    const int kcol = (lcu & 3) * 8;

    auto issue = [&](int c) {
        if (c < NCH) {
            int k0 = c << 5;
            uint32_t sb = smb + (c % NSTAGE) * STG;
#pragma unroll
            for (int i = 0; i < BM / 16; i++) {
                int row = lrow + i * 16;
                uint32_t off = swz((uint32_t)(row * 128 + lcu * 16));
                cp16(sb + off, Abase + aPl + (size_t)row * K + k0 + kcol);
            }
#pragma unroll
            for (int i = 0; i < 8; i++) {
                int row = lrow + i * 16;
                uint32_t off = swz((uint32_t)(row * 128 + lcu * 16));
                cp16(sb + A_STG + off, Bbase + bPl + (size_t)row * K + k0 + kcol);
            }
        }
        CP_COMMIT();
    };

    float acc[AFRAG][8][4];
#pragma unroll
    for (int i = 0; i < AFRAG; i++)
#pragma unroll
        for (int j = 0; j < 8; j++)
#pragma unroll
            for (int v = 0; v < 4; v++) acc[i][j][v] = 0.f;

    issue(0);
    issue(1);

    const int a_row = wm * WROWS + (lane & 7) + ((lane >> 3) & 1) * 8;
    const int a_kb  = ((lane >> 4) & 1) * 16;
    const int b_row = wn * 64 + (lane & 7) + ((lane >> 4) & 1) * 8;
    const int b_kb  = ((lane >> 3) & 1) * 16;

    for (int c = 0; c < NCH; c++) {
        CP_WAIT1();
        __syncthreads();
        issue(c + 2);

        uint32_t sA = smb + (c % NSTAGE) * STG;
        uint32_t sB = sA + A_STG;

#pragma unroll
        for (int ks = 0; ks < 2; ks++) {
            uint32_t a0[AFRAG][4], a1[AFRAG][4];
#pragma unroll
            for (int i = 0; i < AFRAG; i++) {
                uint32_t base = (uint32_t)((a_row + i * 16) * 128 + ks * 32 + a_kb);
                ldsm_x4(a0[i][0], a0[i][1], a0[i][2], a0[i][3], sA + swz(base));
                ldsm_x4(a1[i][0], a1[i][1], a1[i][2], a1[i][3], sA + swz(base + 64));
            }
            uint32_t b0[8][2], b1[8][2];
#pragma unroll
            for (int j2 = 0; j2 < 4; j2++) {
                uint32_t base = (uint32_t)((b_row + j2 * 16) * 128 + ks * 32 + b_kb);
                ldsm_x4(b0[2 * j2][0], b0[2 * j2][1], b0[2 * j2 + 1][0],
                        b0[2 * j2 + 1][1], sB + swz(base));
                ldsm_x4(b1[2 * j2][0], b1[2 * j2][1], b1[2 * j2 + 1][0],
                        b1[2 * j2 + 1][1], sB + swz(base + 64));
            }
#pragma unroll
            for (int i = 0; i < AFRAG; i++)
#pragma unroll
                for (int j = 0; j < 8; j++)
                    mma16816(acc[i][j], a0[i], b1[j]);
#pragma unroll
            for (int i = 0; i < AFRAG; i++)
#pragma unroll
                for (int j = 0; j < 8; j++)
                    mma16816(acc[i][j], a1[i], b0[j]);
#pragma unroll
            for (int i = 0; i < AFRAG; i++)
#pragma unroll
                for (int j = 0; j < 8; j++)
                    mma16816(acc[i][j], a0[i], b0[j]);
        }
    }

    // ---- epilogue ----
    const int r0    = bm + wm * WROWS + (lane >> 2);
    const int cbase = bn + wn * 64 + (lane & 3) * 2;

#pragma unroll
    for (int i = 0; i < AFRAG; i++) {
        const int rowA = r0 + i * 16;
        const int rowL = rowA - rowOff;
#pragma unroll
        for (int j = 0; j < 8; j++) {
            const int col = cbase + j * 8;
            float v0 = acc[i][j][0], v1 = acc[i][j][1];
            float v2 = acc[i][j][2], v3 = acc[i][j][3];
            if (mode == 0) {
                float b0 = bias[col], b1 = bias[col + 1];
                *(float2*)(Cb + (size_t)rowL * ld + col)       = make_float2(v0 + b0, v1 + b1);
                *(float2*)(Cb + (size_t)(rowL + 8) * ld + col) = make_float2(v2 + b0, v3 + b1);
            } else if (mode == 1) {
                float2* p0 = (float2*)(Cb + (size_t)rowL * ld + col);
                float2* p1 = (float2*)(Cb + (size_t)(rowL + 8) * ld + col);
                float2 o0 = *p0, o1 = *p1;
                *p0 = make_float2(o0.x + v0, o0.y + v1);
                *p1 = make_float2(o1.x + v2, o1.y + v3);
            } else {
                float b0 = bias[col], b1 = bias[col + 1];
                const float2 u0 = *(const float2*)(U + (size_t)rowL * ld + col);
                const float2 u1 = *(const float2*)(U + (size_t)(rowL + 8) * ld + col);
                float p00 = fmaxf(v0 + b0, 0.f), p01 = fmaxf(v1 + b1, 0.f);
                float p10 = fmaxf(v2 + b0, 0.f), p11 = fmaxf(v3 + b1, 0.f);
                *(float2*)(Out + (size_t)rowL * ld + col) =
                    make_float2(u0.x < p00 ? 1.f : 0.f, u0.y < p01 ? 1.f : 0.f);
                *(float2*)(Out + (size_t)(rowL + 8) * ld + col) =
                    make_float2(u1.x < p10 ? 1.f : 0.f, u1.y < p11 ? 1.f : 0.f);
            }
        }
    }
}

#define GSMEM128 (NSTAGE * (128 * 128 + 16384))   // 98304
#define GSMEM64  (NSTAGE * (64 * 128 + 16384))    // 73728

// ===========================================================================
extern "C" void kernel_launch(void* const* d_in, const int* in_sizes, int n_in,
                              void* d_out, int out_size)
{
    const float* state = (const float*)d_in[0];
    const float* goal  = (const float*)d_in[1];
    const float* u     = (const float*)d_in[2];
    const float* Wih1  = (const float*)d_in[3];
    const float* Whh1  = (const float*)d_in[4];
    const float* bih1  = (const float*)d_in[5];
    const float* bhh1  = (const float*)d_in[6];
    const float* Wih2  = (const float*)d_in[7];
    const float* bih2  = (const float*)d_in[9];
    const float* bhh2  = (const float*)d_in[10];
    const float* Wih3  = (const float*)d_in[11];
    const float* bih3  = (const float*)d_in[13];
    const float* bhh3  = (const float*)d_in[14];
    const float* Wih4  = (const float*)d_in[15];
    const float* bih4  = (const float*)d_in[17];
    const float* bhh4  = (const float*)d_in[18];
    const float* Wout  = (const float*)d_in[19];
    const float* bout  = (const float*)d_in[20];
    float* out = (float*)d_out;

    __half *XA, *W1, *Whh, *W2, *W3, *W4, *Wo, *Hs;
    float *G, *c1, *bias;
    cudaGetSymbolAddress((void**)&XA,  g_XA);
    cudaGetSymbolAddress((void**)&W1,  g_W1);
    cudaGetSymbolAddress((void**)&Whh, g_Whh);
    cudaGetSymbolAddress((void**)&W2,  g_W2);
    cudaGetSymbolAddress((void**)&W3,  g_W3);
    cudaGetSymbolAddress((void**)&W4,  g_W4);
    cudaGetSymbolAddress((void**)&Wo,  g_Wo);
    cudaGetSymbolAddress((void**)&Hs,  g_Hs);
    cudaGetSymbolAddress((void**)&G,   g_G);
    cudaGetSymbolAddress((void**)&c1,  g_c1);
    cudaGetSymbolAddress((void**)&bias, g_bias);

    cudaFuncSetAttribute(mma_gemm<128, 1>,
                         cudaFuncAttributeMaxDynamicSharedMemorySize, GSMEM128);
    cudaFuncSetAttribute(mma_gemm<64, 0>,
                         cudaFuncAttributeMaxDynamicSharedMemorySize, GSMEM64);

    const size_t SX  = (size_t)8192 * 3072;
    const size_t SWs = (size_t)2048 * 512;
    const size_t SWp = (size_t)NPRU * 512;
    const size_t SH  = (size_t)4096 * 512;
    float* G0 = G;                                   // 4096 x 1536 (t0 igo)
    float* G1 = G + (size_t)4096 * 1536;             // 4096 x 2048 (t1 igof)
    float* b1r = bias;
    float* b2p = bias + 2048;
    float* b3p = b2p + NPRU;
    float* b4p = b3p + NPRU;

    // ---- fused preprocessing (one launch) ----
    prep_all_kernel<<<BX5, 256>>>(
        state, goal, Wih1, Whh1, Wih2, Wih3, Wih4, Wout,
        bih1, bhh1, bih2, bhh2, bih3, bhh3, bih4, bhh4,
        XA, W1, Whh, W2, W3, W4, Wo, bias);

    // ---- big GEMM (ragged): 768 igo tiles + 128 t1-f tiles ----
    mma_gemm<128, 1><<<896, 128, GSMEM128>>>(
        XA, SX, W1, (size_t)2048 * 3072, G0, G1, b1r, nullptr, nullptr,
        8192, 2048, 3072, 0);

    // cell1 @ t=0 (G0: [i|g|o], stride 1536)
    cell_zero_kernel<<<BATCH * HID / 4 / 256, 256>>>(G0, 1536, 512, 1024, Hs, SH, c1);

    // G1 += h1 @ Whh^T  ([i|g|o|f], N=2048) — BM=64 (3 CTAs/SM, 12 warps)
    mma_gemm<64, 0><<<dim3(2048 / 128, 4096 / 64), 128, GSMEM64>>>(
        Hs, SH, Whh, SWs, G1, nullptr, nullptr, nullptr, nullptr,
        4096, 2048, 512, 1);

    // cell1 @ t=1 (G1: [i|g|o|f])
    cell_step_kernel<<<BATCH * HID / 4 / 256, 256>>>(G1, c1, Hs, SH);

    // ---- pruned layers (N=1536, [i|g|o]) on BM=64 ----
    mma_gemm<64, 0><<<dim3(NPRU / 128, 4096 / 64), 128, GSMEM64>>>(
        Hs, SH, W2, SWp, G0, nullptr, b2p, nullptr, nullptr, 4096, NPRU, 512, 0);
    cell_zero_kernel<<<BATCH * HID / 4 / 256, 256>>>(G0, NPRU, 512, 1024, Hs, SH, nullptr);

    mma_gemm<64, 0><<<dim3(NPRU / 128, 4096 / 64), 128, GSMEM64>>>(
        Hs, SH, W3, SWp, G0, nullptr, b3p, nullptr, nullptr, 4096, NPRU, 512, 0);
    cell_zero_kernel<<<BATCH * HID / 4 / 256, 256>>>(G0, NPRU, 512, 1024, Hs, SH, nullptr);

    mma_gemm<64, 0><<<dim3(NPRU / 128, 4096 / 64), 128, GSMEM64>>>(
        Hs, SH, W4, SWp, G0, nullptr, b4p, nullptr, nullptr, 4096, NPRU, 512, 0);
    cell_zero_kernel<<<BATCH * HID / 4 / 256, 256>>>(G0, NPRU, 512, 1024, Hs, SH, nullptr);

    // ---- head: out = (u < relu(h4 @ Wout^T + bout)) ----
    mma_gemm<64, 0><<<dim3(512 / 128, 4096 / 64), 128, GSMEM64>>>(
        Hs, SH, Wo, (size_t)512 * 512, nullptr, nullptr, bout, u, out,
        4096, 512, 512, 2);
}